// round 7
// baseline (speedup 1.0000x reference)
#include <cuda_runtime.h>

// KNNInterpolate, 2-pass latency-split:
//   weights: 1 query per thread (proven best), writes interleaved {idx4, w4}
//            32-byte metadata records.
//   gather:  persistent grid-stride warps, 2 queries per iteration: meta loads
//            for iteration n+1 overlap stores of iteration n -> continuous
//            6-wide gather stream, no per-warp startup/drain bubbles.
//
// Inputs (metadata order):
//   d_in[0] s_feats          float32 [65536, 128]
//   d_in[1] q_points         float32 [262144, 3]
//   d_in[2] s_points         float32 [65536, 3]
//   d_in[3] neighbor_indices int32   [262144, 3]
// Output: float32 [262144, 128]

#define C_FEAT 128
#define N_SRC 65536
#define M_QRY 262144
#define EPS 1e-8f

struct Meta {          // 32B, 16B-aligned: idx + weights share a 128B line
    int4 idx;
    float4 w;
};
__device__ Meta g_meta[M_QRY];

__device__ __forceinline__ float wgt3(const float* __restrict__ sp, int i,
                                      float qx, float qy, float qz)
{
    float dx = qx - __ldg(sp + 3ll * i + 0);
    float dy = qy - __ldg(sp + 3ll * i + 1);
    float dz = qz - __ldg(sp + 3ll * i + 2);
    return 1.0f / (dx * dx + dy * dy + dz * dz + EPS);
}

// One thread per query: compute weights, store packed metadata.
__global__ __launch_bounds__(256) void weights_kernel(
    const float* __restrict__ q_points,
    const float* __restrict__ s_points,
    const int* __restrict__ nidx,
    int M)
{
    int m = blockIdx.x * blockDim.x + threadIdx.x;
    if (m >= M) return;

    const int i0 = __ldg(nidx + 3ll * m + 0);
    const int i1 = __ldg(nidx + 3ll * m + 1);
    const int i2 = __ldg(nidx + 3ll * m + 2);

    const float qx = __ldg(q_points + 3ll * m + 0);
    const float qy = __ldg(q_points + 3ll * m + 1);
    const float qz = __ldg(q_points + 3ll * m + 2);

    float w0 = wgt3(s_points, i0, qx, qy, qz);
    float w1 = wgt3(s_points, i1, qx, qy, qz);
    float w2 = wgt3(s_points, i2, qx, qy, qz);
    const float s = 1.0f / (w0 + w1 + w2);

    g_meta[m].idx = make_int4(i0, i1, i2, 0);
    g_meta[m].w = make_float4(w0 * s, w1 * s, w2 * s, 0.0f);
}

__device__ __forceinline__ float4 wsum(float4 a, float4 b, float4 c, float4 w)
{
    float4 r;
    r.x = w.x * a.x; r.y = w.x * a.y; r.z = w.x * a.z; r.w = w.x * a.w;
    r.x = fmaf(w.y, b.x, r.x); r.y = fmaf(w.y, b.y, r.y);
    r.z = fmaf(w.y, b.z, r.z); r.w = fmaf(w.y, b.w, r.w);
    r.x = fmaf(w.z, c.x, r.x); r.y = fmaf(w.z, c.y, r.y);
    r.z = fmaf(w.z, c.z, r.z); r.w = fmaf(w.z, c.w, r.w);
    return r;
}

// Persistent grid-stride warps; 2 queries per iteration.
__global__ __launch_bounds__(256) void gather_kernel(
    const float* __restrict__ s_feats,
    float4* __restrict__ out,
    int n_pairs)
{
    const int warp0 = (int)((blockIdx.x * blockDim.x + threadIdx.x) >> 5);
    const int lane = threadIdx.x & 31;
    const int n_warps = (int)((gridDim.x * blockDim.x) >> 5);

    const float4* sfl = (const float4*)s_feats + lane;  // lane-offset base

    for (int pair = warp0; pair < n_pairs; pair += n_warps) {
        const int m0 = 2 * pair;

        // broadcast meta (two 16B loads per query, same 128B line)
        const int4 iv0 = __ldg(&g_meta[m0].idx);
        const float4 wv0 = __ldg(&g_meta[m0].w);
        const int4 iv1 = __ldg(&g_meta[m0 + 1].idx);
        const float4 wv1 = __ldg(&g_meta[m0 + 1].w);

        // six independent row gathers in flight
        const float4 a0 = __ldg(sfl + (long long)iv0.x * (C_FEAT / 4));
        const float4 b0 = __ldg(sfl + (long long)iv0.y * (C_FEAT / 4));
        const float4 c0 = __ldg(sfl + (long long)iv0.z * (C_FEAT / 4));
        const float4 a1 = __ldg(sfl + (long long)iv1.x * (C_FEAT / 4));
        const float4 b1 = __ldg(sfl + (long long)iv1.y * (C_FEAT / 4));
        const float4 c1 = __ldg(sfl + (long long)iv1.z * (C_FEAT / 4));

        float4* o = out + (long long)m0 * (C_FEAT / 4) + lane;
        __stcs(o, wsum(a0, b0, c0, wv0));
        __stcs(o + (C_FEAT / 4), wsum(a1, b1, c1, wv1));
    }
}

extern "C" void kernel_launch(void* const* d_in, const int* in_sizes, int n_in,
                              void* d_out, int out_size)
{
    const float* s_feats = (const float*)d_in[0];
    const float* q_points = (const float*)d_in[1];
    const float* s_points = (const float*)d_in[2];
    const int* nidx = (const int*)d_in[3];
    float4* out = (float4*)d_out;

    const int M = in_sizes[1] / 3;   // 262144
    const int n_pairs = M / 2;       // 131072

    weights_kernel<<<(M + 255) / 256, 256>>>(q_points, s_points, nidx, M);

    // Persistent-ish: 2048 blocks x 8 warps = 16384 warps, 8 pairs per warp.
    const int blocks = 2048;
    gather_kernel<<<blocks, 256>>>(s_feats, out, n_pairs);
}

// round 8
// speedup vs baseline: 1.0091x; 1.0091x over previous
#include <cuda_runtime.h>

// KNNInterpolate, 2-pass latency-split:
//   weights: 1 query per thread (proven best), writes interleaved {idx4, w4}
//            32-byte metadata records.
//   gather:  persistent grid-stride warps, 2 queries per iteration: meta loads
//            for iteration n+1 overlap stores of iteration n -> continuous
//            6-wide gather stream, no per-warp startup/drain bubbles.
//
// Inputs (metadata order):
//   d_in[0] s_feats          float32 [65536, 128]
//   d_in[1] q_points         float32 [262144, 3]
//   d_in[2] s_points         float32 [65536, 3]
//   d_in[3] neighbor_indices int32   [262144, 3]
// Output: float32 [262144, 128]

#define C_FEAT 128
#define N_SRC 65536
#define M_QRY 262144
#define EPS 1e-8f

struct Meta {          // 32B, 16B-aligned: idx + weights share a 128B line
    int4 idx;
    float4 w;
};
__device__ Meta g_meta[M_QRY];

__device__ __forceinline__ float wgt3(const float* __restrict__ sp, int i,
                                      float qx, float qy, float qz)
{
    float dx = qx - __ldg(sp + 3ll * i + 0);
    float dy = qy - __ldg(sp + 3ll * i + 1);
    float dz = qz - __ldg(sp + 3ll * i + 2);
    return 1.0f / (dx * dx + dy * dy + dz * dz + EPS);
}

// One thread per query: compute weights, store packed metadata.
__global__ __launch_bounds__(256) void weights_kernel(
    const float* __restrict__ q_points,
    const float* __restrict__ s_points,
    const int* __restrict__ nidx,
    int M)
{
    int m = blockIdx.x * blockDim.x + threadIdx.x;
    if (m >= M) return;

    const int i0 = __ldg(nidx + 3ll * m + 0);
    const int i1 = __ldg(nidx + 3ll * m + 1);
    const int i2 = __ldg(nidx + 3ll * m + 2);

    const float qx = __ldg(q_points + 3ll * m + 0);
    const float qy = __ldg(q_points + 3ll * m + 1);
    const float qz = __ldg(q_points + 3ll * m + 2);

    float w0 = wgt3(s_points, i0, qx, qy, qz);
    float w1 = wgt3(s_points, i1, qx, qy, qz);
    float w2 = wgt3(s_points, i2, qx, qy, qz);
    const float s = 1.0f / (w0 + w1 + w2);

    g_meta[m].idx = make_int4(i0, i1, i2, 0);
    g_meta[m].w = make_float4(w0 * s, w1 * s, w2 * s, 0.0f);
}

__device__ __forceinline__ float4 wsum(float4 a, float4 b, float4 c, float4 w)
{
    float4 r;
    r.x = w.x * a.x; r.y = w.x * a.y; r.z = w.x * a.z; r.w = w.x * a.w;
    r.x = fmaf(w.y, b.x, r.x); r.y = fmaf(w.y, b.y, r.y);
    r.z = fmaf(w.y, b.z, r.z); r.w = fmaf(w.y, b.w, r.w);
    r.x = fmaf(w.z, c.x, r.x); r.y = fmaf(w.z, c.y, r.y);
    r.z = fmaf(w.z, c.z, r.z); r.w = fmaf(w.z, c.w, r.w);
    return r;
}

// Persistent grid-stride warps; 2 queries per iteration.
__global__ __launch_bounds__(256) void gather_kernel(
    const float* __restrict__ s_feats,
    float4* __restrict__ out,
    int n_pairs)
{
    const int warp0 = (int)((blockIdx.x * blockDim.x + threadIdx.x) >> 5);
    const int lane = threadIdx.x & 31;
    const int n_warps = (int)((gridDim.x * blockDim.x) >> 5);

    const float4* sfl = (const float4*)s_feats + lane;  // lane-offset base

    for (int pair = warp0; pair < n_pairs; pair += n_warps) {
        const int m0 = 2 * pair;

        // broadcast meta (two 16B loads per query, same 128B line)
        const int4 iv0 = __ldg(&g_meta[m0].idx);
        const float4 wv0 = __ldg(&g_meta[m0].w);
        const int4 iv1 = __ldg(&g_meta[m0 + 1].idx);
        const float4 wv1 = __ldg(&g_meta[m0 + 1].w);

        // six independent row gathers in flight
        const float4 a0 = __ldg(sfl + (long long)iv0.x * (C_FEAT / 4));
        const float4 b0 = __ldg(sfl + (long long)iv0.y * (C_FEAT / 4));
        const float4 c0 = __ldg(sfl + (long long)iv0.z * (C_FEAT / 4));
        const float4 a1 = __ldg(sfl + (long long)iv1.x * (C_FEAT / 4));
        const float4 b1 = __ldg(sfl + (long long)iv1.y * (C_FEAT / 4));
        const float4 c1 = __ldg(sfl + (long long)iv1.z * (C_FEAT / 4));

        float4* o = out + (long long)m0 * (C_FEAT / 4) + lane;
        __stcs(o, wsum(a0, b0, c0, wv0));
        __stcs(o + (C_FEAT / 4), wsum(a1, b1, c1, wv1));
    }
}

extern "C" void kernel_launch(void* const* d_in, const int* in_sizes, int n_in,
                              void* d_out, int out_size)
{
    const float* s_feats = (const float*)d_in[0];
    const float* q_points = (const float*)d_in[1];
    const float* s_points = (const float*)d_in[2];
    const int* nidx = (const int*)d_in[3];
    float4* out = (float4*)d_out;

    const int M = in_sizes[1] / 3;   // 262144
    const int n_pairs = M / 2;       // 131072

    weights_kernel<<<(M + 255) / 256, 256>>>(q_points, s_points, nidx, M);

    // Persistent-ish: 2048 blocks x 8 warps = 16384 warps, 8 pairs per warp.
    const int blocks = 2048;
    gather_kernel<<<blocks, 256>>>(s_feats, out, n_pairs);
}

// round 9
// speedup vs baseline: 1.1678x; 1.1573x over previous
#include <cuda_runtime.h>
#include <cuda_fp16.h>

// KNNInterpolate — L2-traffic-optimized 2-kernel pipeline.
//
// Finding (R5-R7): the gather pass is LTS(L2)-bandwidth-capped (~6300 B/cyc
// chip-wide). So: gather from an fp16 copy of s_feats (halves the dominant
// read stream), and hide the fp32->fp16 conversion by fusing it with the
// (latency-bound) weights pass in one kernel, split by blockIdx.
//
// Inputs (metadata order):
//   d_in[0] s_feats          float32 [65536, 128]
//   d_in[1] q_points         float32 [262144, 3]
//   d_in[2] s_points         float32 [65536, 3]
//   d_in[3] neighbor_indices int32   [262144, 3]
// Output: float32 [262144, 128]

#define C_FEAT 128
#define N_SRC 65536
#define M_QRY 262144
#define EPS 1e-8f

// fp16 feature table: 65536 x 128 halfs = 16 MB, as uint4 for 16B stores.
#define FEATS_U4 (N_SRC * C_FEAT / 8)
__device__ uint4 g_feats_h[FEATS_U4];

struct Meta {          // 32B: idx + weights share a 128B line
    int4 idx;
    float4 w;
};
__device__ Meta g_meta[M_QRY];

__device__ __forceinline__ float wgt3(const float* __restrict__ sp, int i,
                                      float qx, float qy, float qz)
{
    float dx = qx - __ldg(sp + 3ll * i + 0);
    float dy = qy - __ldg(sp + 3ll * i + 1);
    float dz = qz - __ldg(sp + 3ll * i + 2);
    return 1.0f / (dx * dx + dy * dy + dz * dz + EPS);
}

__device__ __forceinline__ unsigned pack_h2(float a, float b)
{
    __half2 h = __floats2half2_rn(a, b);
    return *reinterpret_cast<unsigned*>(&h);
}

#define CONV_BLOCKS 4096   // FEATS_U4 / 256
#define WGT_BLOCKS  1024   // M_QRY / 256

// Fused prep: blocks [0, WGT_BLOCKS) compute weights; the rest convert feats.
__global__ __launch_bounds__(256) void prep_kernel(
    const float* __restrict__ s_feats,
    const float* __restrict__ q_points,
    const float* __restrict__ s_points,
    const int* __restrict__ nidx,
    int M)
{
    if (blockIdx.x < WGT_BLOCKS) {
        // ---- weights: one thread per query ----
        const int m = blockIdx.x * 256 + threadIdx.x;
        if (m >= M) return;

        const int i0 = __ldg(nidx + 3ll * m + 0);
        const int i1 = __ldg(nidx + 3ll * m + 1);
        const int i2 = __ldg(nidx + 3ll * m + 2);

        const float qx = __ldg(q_points + 3ll * m + 0);
        const float qy = __ldg(q_points + 3ll * m + 1);
        const float qz = __ldg(q_points + 3ll * m + 2);

        float w0 = wgt3(s_points, i0, qx, qy, qz);
        float w1 = wgt3(s_points, i1, qx, qy, qz);
        float w2 = wgt3(s_points, i2, qx, qy, qz);
        const float s = 1.0f / (w0 + w1 + w2);

        g_meta[m].idx = make_int4(i0, i1, i2, 0);
        g_meta[m].w = make_float4(w0 * s, w1 * s, w2 * s, 0.0f);
    } else {
        // ---- conversion: one thread per 8 floats (2x LDG.128 -> 1x STG.128) ----
        const int t = (blockIdx.x - WGT_BLOCKS) * 256 + threadIdx.x;
        if (t >= FEATS_U4) return;
        const float4* src = (const float4*)s_feats;
        const float4 f0 = __ldg(src + 2ll * t);
        const float4 f1 = __ldg(src + 2ll * t + 1);
        uint4 p;
        p.x = pack_h2(f0.x, f0.y);
        p.y = pack_h2(f0.z, f0.w);
        p.z = pack_h2(f1.x, f1.y);
        p.w = pack_h2(f1.z, f1.w);
        g_feats_h[t] = p;
    }
}

// Weighted sum of three fp16 4-channel chunks (fp32 accumulate).
__device__ __forceinline__ float4 wsum_h(uint2 ga, uint2 gb, uint2 gc, float4 w)
{
    const float2 a01 = __half22float2(*reinterpret_cast<__half2*>(&ga.x));
    const float2 a23 = __half22float2(*reinterpret_cast<__half2*>(&ga.y));
    const float2 b01 = __half22float2(*reinterpret_cast<__half2*>(&gb.x));
    const float2 b23 = __half22float2(*reinterpret_cast<__half2*>(&gb.y));
    const float2 c01 = __half22float2(*reinterpret_cast<__half2*>(&gc.x));
    const float2 c23 = __half22float2(*reinterpret_cast<__half2*>(&gc.y));
    float4 r;
    r.x = w.x * a01.x; r.y = w.x * a01.y; r.z = w.x * a23.x; r.w = w.x * a23.y;
    r.x = fmaf(w.y, b01.x, r.x); r.y = fmaf(w.y, b01.y, r.y);
    r.z = fmaf(w.y, b23.x, r.z); r.w = fmaf(w.y, b23.y, r.w);
    r.x = fmaf(w.z, c01.x, r.x); r.y = fmaf(w.z, c01.y, r.y);
    r.z = fmaf(w.z, c23.x, r.z); r.w = fmaf(w.z, c23.y, r.w);
    return r;
}

// One warp per TWO queries; each lane owns 4 channels (8B fp16 per gather).
__global__ __launch_bounds__(256) void gather_kernel(
    float4* __restrict__ out,
    int n_pairs)
{
    const int pair = (int)((blockIdx.x * blockDim.x + threadIdx.x) >> 5);
    const int lane = threadIdx.x & 31;
    if (pair >= n_pairs) return;

    const int m0 = 2 * pair;

    const int4 iv0 = __ldg(&g_meta[m0].idx);
    const float4 wv0 = __ldg(&g_meta[m0].w);
    const int4 iv1 = __ldg(&g_meta[m0 + 1].idx);
    const float4 wv1 = __ldg(&g_meta[m0 + 1].w);

    // fp16 row = 32 uint2 (256B); lane's chunk = uint2 at [row*32 + lane]
    const uint2* sfl = (const uint2*)g_feats_h + lane;

    const uint2 a0 = __ldg(sfl + 32ll * iv0.x);
    const uint2 b0 = __ldg(sfl + 32ll * iv0.y);
    const uint2 c0 = __ldg(sfl + 32ll * iv0.z);
    const uint2 a1 = __ldg(sfl + 32ll * iv1.x);
    const uint2 b1 = __ldg(sfl + 32ll * iv1.y);
    const uint2 c1 = __ldg(sfl + 32ll * iv1.z);

    float4* o = out + (long long)m0 * (C_FEAT / 4) + lane;
    __stcs(o, wsum_h(a0, b0, c0, wv0));
    __stcs(o + (C_FEAT / 4), wsum_h(a1, b1, c1, wv1));
}

extern "C" void kernel_launch(void* const* d_in, const int* in_sizes, int n_in,
                              void* d_out, int out_size)
{
    const float* s_feats = (const float*)d_in[0];
    const float* q_points = (const float*)d_in[1];
    const float* s_points = (const float*)d_in[2];
    const int* nidx = (const int*)d_in[3];
    float4* out = (float4*)d_out;

    const int M = in_sizes[1] / 3;   // 262144
    const int n_pairs = M / 2;

    prep_kernel<<<WGT_BLOCKS + CONV_BLOCKS, 256>>>(
        s_feats, q_points, s_points, nidx, M);

    const int warps_per_block = 8;   // 256 threads
    const int blocks = (n_pairs + warps_per_block - 1) / warps_per_block;
    gather_kernel<<<blocks, warps_per_block * 32>>>(out, n_pairs);
}

// round 10
// speedup vs baseline: 1.1985x; 1.0263x over previous
#include <cuda_runtime.h>
#include <cuda_fp16.h>

// KNNInterpolate — L2-traffic-optimized 2-kernel pipeline.
//
// R9 finding: gather pass sits at the LTS chip cap (~6300 B/cyc) with
// compulsory traffic (192 MB fp16 gather reads + 128 MB fp32 stores) -> it is
// at its floor (~28-30us). R10 attacks the prep pass: conversion now does 4
// independent 16B records per thread (MLP 2 -> 8) to reach DRAM-bound rate,
// and conversion blocks launch before weights blocks.
//
// Inputs (metadata order):
//   d_in[0] s_feats          float32 [65536, 128]
//   d_in[1] q_points         float32 [262144, 3]
//   d_in[2] s_points         float32 [65536, 3]
//   d_in[3] neighbor_indices int32   [262144, 3]
// Output: float32 [262144, 128]

#define C_FEAT 128
#define N_SRC 65536
#define M_QRY 262144
#define EPS 1e-8f

// fp16 feature table: 65536 x 128 halfs = 16 MB, as uint4 for 16B stores.
#define FEATS_U4 (N_SRC * C_FEAT / 8)   // 1048576
__device__ uint4 g_feats_h[FEATS_U4];

struct Meta {          // 32B: idx + weights share a 128B line
    int4 idx;
    float4 w;
};
__device__ Meta g_meta[M_QRY];

__device__ __forceinline__ float wgt3(const float* __restrict__ sp, int i,
                                      float qx, float qy, float qz)
{
    float dx = qx - __ldg(sp + 3ll * i + 0);
    float dy = qy - __ldg(sp + 3ll * i + 1);
    float dz = qz - __ldg(sp + 3ll * i + 2);
    return 1.0f / (dx * dx + dy * dy + dz * dz + EPS);
}

__device__ __forceinline__ unsigned pack_h2(float a, float b)
{
    __half2 h = __floats2half2_rn(a, b);
    return *reinterpret_cast<unsigned*>(&h);
}

// 4 records per conversion thread: FEATS_U4 / 4 / 256 = 1024 blocks.
#define CONV_PER_THREAD 4
#define CONV_THREADS (FEATS_U4 / CONV_PER_THREAD)   // 262144
#define CONV_BLOCKS (CONV_THREADS / 256)            // 1024
#define WGT_BLOCKS  (M_QRY / 256)                   // 1024

// Fused prep. Conversion blocks FIRST (DRAM stream starts immediately),
// weights blocks after.
__global__ __launch_bounds__(256) void prep_kernel(
    const float* __restrict__ s_feats,
    const float* __restrict__ q_points,
    const float* __restrict__ s_points,
    const int* __restrict__ nidx,
    int M)
{
    if (blockIdx.x < CONV_BLOCKS) {
        // ---- conversion: 4 independent coalesced 16B records per thread ----
        const int t = blockIdx.x * 256 + threadIdx.x;
        const float4* src = (const float4*)s_feats;
        #pragma unroll
        for (int k = 0; k < CONV_PER_THREAD; k++) {
            const long long r = t + (long long)k * CONV_THREADS;
            const float4 f0 = __ldg(src + 2 * r);
            const float4 f1 = __ldg(src + 2 * r + 1);
            uint4 p;
            p.x = pack_h2(f0.x, f0.y);
            p.y = pack_h2(f0.z, f0.w);
            p.z = pack_h2(f1.x, f1.y);
            p.w = pack_h2(f1.z, f1.w);
            g_feats_h[r] = p;
        }
    } else {
        // ---- weights: one thread per query ----
        const int m = (blockIdx.x - CONV_BLOCKS) * 256 + threadIdx.x;
        if (m >= M) return;

        const int i0 = __ldg(nidx + 3ll * m + 0);
        const int i1 = __ldg(nidx + 3ll * m + 1);
        const int i2 = __ldg(nidx + 3ll * m + 2);

        const float qx = __ldg(q_points + 3ll * m + 0);
        const float qy = __ldg(q_points + 3ll * m + 1);
        const float qz = __ldg(q_points + 3ll * m + 2);

        float w0 = wgt3(s_points, i0, qx, qy, qz);
        float w1 = wgt3(s_points, i1, qx, qy, qz);
        float w2 = wgt3(s_points, i2, qx, qy, qz);
        const float s = 1.0f / (w0 + w1 + w2);

        g_meta[m].idx = make_int4(i0, i1, i2, 0);
        g_meta[m].w = make_float4(w0 * s, w1 * s, w2 * s, 0.0f);
    }
}

// Weighted sum of three fp16 4-channel chunks (fp32 accumulate).
__device__ __forceinline__ float4 wsum_h(uint2 ga, uint2 gb, uint2 gc, float4 w)
{
    const float2 a01 = __half22float2(*reinterpret_cast<__half2*>(&ga.x));
    const float2 a23 = __half22float2(*reinterpret_cast<__half2*>(&ga.y));
    const float2 b01 = __half22float2(*reinterpret_cast<__half2*>(&gb.x));
    const float2 b23 = __half22float2(*reinterpret_cast<__half2*>(&gb.y));
    const float2 c01 = __half22float2(*reinterpret_cast<__half2*>(&gc.x));
    const float2 c23 = __half22float2(*reinterpret_cast<__half2*>(&gc.y));
    float4 r;
    r.x = w.x * a01.x; r.y = w.x * a01.y; r.z = w.x * a23.x; r.w = w.x * a23.y;
    r.x = fmaf(w.y, b01.x, r.x); r.y = fmaf(w.y, b01.y, r.y);
    r.z = fmaf(w.y, b23.x, r.z); r.w = fmaf(w.y, b23.y, r.w);
    r.x = fmaf(w.z, c01.x, r.x); r.y = fmaf(w.z, c01.y, r.y);
    r.z = fmaf(w.z, c23.x, r.z); r.w = fmaf(w.z, c23.y, r.w);
    return r;
}

// One warp per TWO queries; each lane owns 4 channels (8B fp16 per gather).
__global__ __launch_bounds__(256) void gather_kernel(
    float4* __restrict__ out,
    int n_pairs)
{
    const int pair = (int)((blockIdx.x * blockDim.x + threadIdx.x) >> 5);
    const int lane = threadIdx.x & 31;
    if (pair >= n_pairs) return;

    const int m0 = 2 * pair;

    const int4 iv0 = __ldg(&g_meta[m0].idx);
    const float4 wv0 = __ldg(&g_meta[m0].w);
    const int4 iv1 = __ldg(&g_meta[m0 + 1].idx);
    const float4 wv1 = __ldg(&g_meta[m0 + 1].w);

    // fp16 row = 32 uint2 (256B); lane's chunk = uint2 at [row*32 + lane]
    const uint2* sfl = (const uint2*)g_feats_h + lane;

    const uint2 a0 = __ldg(sfl + 32ll * iv0.x);
    const uint2 b0 = __ldg(sfl + 32ll * iv0.y);
    const uint2 c0 = __ldg(sfl + 32ll * iv0.z);
    const uint2 a1 = __ldg(sfl + 32ll * iv1.x);
    const uint2 b1 = __ldg(sfl + 32ll * iv1.y);
    const uint2 c1 = __ldg(sfl + 32ll * iv1.z);

    float4* o = out + (long long)m0 * (C_FEAT / 4) + lane;
    __stcs(o, wsum_h(a0, b0, c0, wv0));
    __stcs(o + (C_FEAT / 4), wsum_h(a1, b1, c1, wv1));
}

extern "C" void kernel_launch(void* const* d_in, const int* in_sizes, int n_in,
                              void* d_out, int out_size)
{
    const float* s_feats = (const float*)d_in[0];
    const float* q_points = (const float*)d_in[1];
    const float* s_points = (const float*)d_in[2];
    const int* nidx = (const int*)d_in[3];
    float4* out = (float4*)d_out;

    const int M = in_sizes[1] / 3;   // 262144
    const int n_pairs = M / 2;

    prep_kernel<<<CONV_BLOCKS + WGT_BLOCKS, 256>>>(
        s_feats, q_points, s_points, nidx, M);

    const int warps_per_block = 8;   // 256 threads
    const int blocks = (n_pairs + warps_per_block - 1) / warps_per_block;
    gather_kernel<<<blocks, warps_per_block * 32>>>(out, n_pairs);
}

// round 11
// speedup vs baseline: 1.2597x; 1.0511x over previous
#include <cuda_runtime.h>
#include <cuda_fp16.h>

// KNNInterpolate — L2-traffic-optimized 2-kernel pipeline.
//
// R10 finding: gather pass is at ~92% of the LTS chip cap with near-compulsory
// traffic; prep near its DRAM floor. R11: compress metadata to 16B/query
// (idx3 + fp16 w0,w1; w2 = 1-w0-w1 so weights still sum to exactly 1), and
// use evict-first loads on read-once streams to keep the fp16 feature table
// L2-resident.
//
// Inputs (metadata order):
//   d_in[0] s_feats          float32 [65536, 128]
//   d_in[1] q_points         float32 [262144, 3]
//   d_in[2] s_points         float32 [65536, 3]
//   d_in[3] neighbor_indices int32   [262144, 3]
// Output: float32 [262144, 128]

#define C_FEAT 128
#define N_SRC 65536
#define M_QRY 262144
#define EPS 1e-8f

// fp16 feature table: 65536 x 128 halfs = 16 MB, as uint4 for 16B stores.
#define FEATS_U4 (N_SRC * C_FEAT / 8)   // 1048576
__device__ uint4 g_feats_h[FEATS_U4];

// 16B metadata: x=i0, y=i1, z=i2, w=half2(w0,w1). w2 reconstructed.
__device__ int4 g_meta[M_QRY];

__device__ __forceinline__ float wgt3(const float* __restrict__ sp, int i,
                                      float qx, float qy, float qz)
{
    float dx = qx - __ldg(sp + 3ll * i + 0);
    float dy = qy - __ldg(sp + 3ll * i + 1);
    float dz = qz - __ldg(sp + 3ll * i + 2);
    return 1.0f / (dx * dx + dy * dy + dz * dz + EPS);
}

__device__ __forceinline__ unsigned pack_h2(float a, float b)
{
    __half2 h = __floats2half2_rn(a, b);
    return *reinterpret_cast<unsigned*>(&h);
}

// 4 records per conversion thread.
#define CONV_PER_THREAD 4
#define CONV_THREADS (FEATS_U4 / CONV_PER_THREAD)   // 262144
#define CONV_BLOCKS (CONV_THREADS / 256)            // 1024
#define WGT_BLOCKS  (M_QRY / 256)                   // 1024

// Fused prep. Conversion blocks FIRST (DRAM stream starts immediately).
__global__ __launch_bounds__(256) void prep_kernel(
    const float* __restrict__ s_feats,
    const float* __restrict__ q_points,
    const float* __restrict__ s_points,
    const int* __restrict__ nidx,
    int M)
{
    if (blockIdx.x < CONV_BLOCKS) {
        // ---- conversion: 4 independent coalesced 16B records per thread ----
        const int t = blockIdx.x * 256 + threadIdx.x;
        const float4* src = (const float4*)s_feats;
        #pragma unroll
        for (int k = 0; k < CONV_PER_THREAD; k++) {
            const long long r = t + (long long)k * CONV_THREADS;
            const float4 f0 = __ldcs(src + 2 * r);      // read-once: evict-first
            const float4 f1 = __ldcs(src + 2 * r + 1);
            uint4 p;
            p.x = pack_h2(f0.x, f0.y);
            p.y = pack_h2(f0.z, f0.w);
            p.z = pack_h2(f1.x, f1.y);
            p.w = pack_h2(f1.z, f1.w);
            g_feats_h[r] = p;                           // default: stays in L2
        }
    } else {
        // ---- weights: one thread per query ----
        const int m = (blockIdx.x - CONV_BLOCKS) * 256 + threadIdx.x;
        if (m >= M) return;

        const int i0 = __ldg(nidx + 3ll * m + 0);
        const int i1 = __ldg(nidx + 3ll * m + 1);
        const int i2 = __ldg(nidx + 3ll * m + 2);

        const float qx = __ldg(q_points + 3ll * m + 0);
        const float qy = __ldg(q_points + 3ll * m + 1);
        const float qz = __ldg(q_points + 3ll * m + 2);

        float w0 = wgt3(s_points, i0, qx, qy, qz);
        float w1 = wgt3(s_points, i1, qx, qy, qz);
        float w2 = wgt3(s_points, i2, qx, qy, qz);
        const float s = 1.0f / (w0 + w1 + w2);

        int4 mv;
        mv.x = i0;
        mv.y = i1;
        mv.z = i2;
        mv.w = (int)pack_h2(w0 * s, w1 * s);
        g_meta[m] = mv;
    }
}

// Weighted sum of three fp16 4-channel chunks (fp32 accumulate).
__device__ __forceinline__ float4 wsum_h(uint2 ga, uint2 gb, uint2 gc,
                                         float w0, float w1, float w2)
{
    const float2 a01 = __half22float2(*reinterpret_cast<__half2*>(&ga.x));
    const float2 a23 = __half22float2(*reinterpret_cast<__half2*>(&ga.y));
    const float2 b01 = __half22float2(*reinterpret_cast<__half2*>(&gb.x));
    const float2 b23 = __half22float2(*reinterpret_cast<__half2*>(&gb.y));
    const float2 c01 = __half22float2(*reinterpret_cast<__half2*>(&gc.x));
    const float2 c23 = __half22float2(*reinterpret_cast<__half2*>(&gc.y));
    float4 r;
    r.x = w0 * a01.x; r.y = w0 * a01.y; r.z = w0 * a23.x; r.w = w0 * a23.y;
    r.x = fmaf(w1, b01.x, r.x); r.y = fmaf(w1, b01.y, r.y);
    r.z = fmaf(w1, b23.x, r.z); r.w = fmaf(w1, b23.y, r.w);
    r.x = fmaf(w2, c01.x, r.x); r.y = fmaf(w2, c01.y, r.y);
    r.z = fmaf(w2, c23.x, r.z); r.w = fmaf(w2, c23.y, r.w);
    return r;
}

// One warp per TWO queries; each lane owns 4 channels (8B fp16 per gather).
__global__ __launch_bounds__(256) void gather_kernel(
    float4* __restrict__ out,
    int n_pairs)
{
    const int pair = (int)((blockIdx.x * blockDim.x + threadIdx.x) >> 5);
    const int lane = threadIdx.x & 31;
    if (pair >= n_pairs) return;

    const int m0 = 2 * pair;

    // 16B meta per query, read-once -> evict-first
    const int4 mv0 = __ldcs(&g_meta[m0]);
    const int4 mv1 = __ldcs(&g_meta[m0 + 1]);

    unsigned pw0 = (unsigned)mv0.w;
    unsigned pw1 = (unsigned)mv1.w;
    const float2 w01a = __half22float2(*reinterpret_cast<__half2*>(&pw0));
    const float2 w01b = __half22float2(*reinterpret_cast<__half2*>(&pw1));
    const float w2a = 1.0f - w01a.x - w01a.y;
    const float w2b = 1.0f - w01b.x - w01b.y;

    // fp16 row = 32 uint2 (256B); lane's chunk = uint2 at [row*32 + lane]
    const uint2* sfl = (const uint2*)g_feats_h + lane;

    const uint2 a0 = __ldg(sfl + 32ll * mv0.x);
    const uint2 b0 = __ldg(sfl + 32ll * mv0.y);
    const uint2 c0 = __ldg(sfl + 32ll * mv0.z);
    const uint2 a1 = __ldg(sfl + 32ll * mv1.x);
    const uint2 b1 = __ldg(sfl + 32ll * mv1.y);
    const uint2 c1 = __ldg(sfl + 32ll * mv1.z);

    float4* o = out + (long long)m0 * (C_FEAT / 4) + lane;
    __stcs(o, wsum_h(a0, b0, c0, w01a.x, w01a.y, w2a));
    __stcs(o + (C_FEAT / 4), wsum_h(a1, b1, c1, w01b.x, w01b.y, w2b));
}

extern "C" void kernel_launch(void* const* d_in, const int* in_sizes, int n_in,
                              void* d_out, int out_size)
{
    const float* s_feats = (const float*)d_in[0];
    const float* q_points = (const float*)d_in[1];
    const float* s_points = (const float*)d_in[2];
    const int* nidx = (const int*)d_in[3];
    float4* out = (float4*)d_out;

    const int M = in_sizes[1] / 3;   // 262144
    const int n_pairs = M / 2;

    prep_kernel<<<CONV_BLOCKS + WGT_BLOCKS, 256>>>(
        s_feats, q_points, s_points, nidx, M);

    const int warps_per_block = 8;   // 256 threads
    const int blocks = (n_pairs + warps_per_block - 1) / warps_per_block;
    gather_kernel<<<blocks, warps_per_block * 32>>>(out, n_pairs);
}